// round 1
// baseline (speedup 1.0000x reference)
#include <cuda_runtime.h>
#include <cstdint>

#define BQ    4
#define NRES  2048
#define TOPK  32
#define NRBF  16
#define EIN   416
#define EFEAT 128
#define NROWS (BQ * NRES)          // 8192
#define NEDGE (NROWS * TOPK)       // 262144

// ---------------- device scratch (no allocs allowed) ----------------
__device__ float g_atoms[NROWS * 15];            // N,Ca,C,O,Cb xyz per residue
__device__ float g_dn[NEDGE];                    // top-k distances
__device__ int   g_eidx[NEDGE];                  // top-k indices
__device__ float g_F[(size_t)NEDGE * EIN];       // edge features, 436 MB

__constant__ int c_pa[24] = {0,2,3,4,1,1,1,1,0,0,0,4,4,3,0,2,3,4,2,3,4,2,3,2};
__constant__ int c_pb[24] = {0,2,3,4,0,2,3,4,2,3,4,2,3,2,1,1,1,1,0,0,0,4,4,3};
__constant__ float c_freq[8] = {
    1.0f, 0.31622776601683794f, 0.1f, 0.031622776601683794f,
    0.01f, 0.0031622776601683794f, 0.001f, 0.00031622776601683794f};

// ---------------- K1: per-residue atoms (N, Ca, C, O, virtual Cb) ----------------
__global__ void atoms_kernel(const float* __restrict__ X) {
    int r = blockIdx.x * blockDim.x + threadIdx.x;
    if (r >= NROWS) return;
    const float* x = X + (size_t)r * 12;
    float Nx = x[0], Ny = x[1], Nz = x[2];
    float Ax = x[3], Ay = x[4], Az = x[5];   // Ca
    float Cx = x[6], Cy = x[7], Cz = x[8];
    float Ox = x[9], Oy = x[10], Oz = x[11];
    float bx = Ax - Nx, by = Ay - Ny, bz = Az - Nz;
    float cx = Cx - Ax, cy = Cy - Ay, cz = Cz - Az;
    float ax = by * cz - bz * cy;
    float ay = bz * cx - bx * cz;
    float az = bx * cy - by * cx;
    float Bx = -0.58273431f * ax + 0.56802827f * bx - 0.54067466f * cx + Ax;
    float By = -0.58273431f * ay + 0.56802827f * by - 0.54067466f * cy + Ay;
    float Bz = -0.58273431f * az + 0.56802827f * bz - 0.54067466f * cz + Az;
    float* o = g_atoms + (size_t)r * 15;
    o[0] = Nx; o[1] = Ny; o[2] = Nz;
    o[3] = Ax; o[4] = Ay; o[5] = Az;
    o[6] = Cx; o[7] = Cy; o[8] = Cz;
    o[9] = Ox; o[10] = Oy; o[11] = Oz;
    o[12] = Bx; o[13] = By; o[14] = Bz;
}

// ---------------- K2: top-32 nearest by Ca distance, per row ----------------
__global__ void __launch_bounds__(256) topk_kernel(const float* __restrict__ X,
                                                   const float* __restrict__ mask,
                                                   float* __restrict__ outIdxF,
                                                   int writeIdx) {
    __shared__ float sD[NRES];
    __shared__ float sWv[8];
    __shared__ int   sWi[8];
    __shared__ float sDmax;

    int row = blockIdx.x;
    int bq = row / NRES, i = row - bq * NRES;
    int tid = threadIdx.x, lane = tid & 31, warp = tid >> 5;
    const float* Xb = X + (size_t)bq * NRES * 12;
    const float* mb = mask + (size_t)bq * NRES;

    float cax = Xb[(size_t)i * 12 + 3];
    float cay = Xb[(size_t)i * 12 + 4];
    float caz = Xb[(size_t)i * 12 + 5];
    float mi = mb[i];

    float lmax = 0.0f;
    for (int j = tid; j < NRES; j += 256) {
        float dx = Xb[(size_t)j * 12 + 3] - cax;
        float dy = Xb[(size_t)j * 12 + 4] - cay;
        float dz = Xb[(size_t)j * 12 + 5] - caz;
        float d = sqrtf(dx * dx + dy * dy + dz * dz + 1e-6f);
        float m2 = mi * mb[j];
        float dm = m2 * d;
        sD[j] = dm;
        lmax = fmaxf(lmax, dm);
    }
    // block max
    #pragma unroll
    for (int off = 16; off; off >>= 1)
        lmax = fmaxf(lmax, __shfl_xor_sync(0xffffffffu, lmax, off));
    if (lane == 0) sWv[warp] = lmax;
    __syncthreads();
    if (tid == 0) {
        float m = sWv[0];
        #pragma unroll
        for (int w = 1; w < 8; w++) m = fmaxf(m, sWv[w]);
        sDmax = m;
    }
    __syncthreads();
    float Dmax = sDmax;
    for (int j = tid; j < NRES; j += 256) {
        float m2 = mi * mb[j];
        sD[j] += (1.0f - m2) * Dmax;
    }
    __syncthreads();

    const float INF = __int_as_float(0x7f800000);
    for (int sel = 0; sel < TOPK; sel++) {
        float best = INF;
        int bidx = 0x7fffffff;
        for (int j = tid; j < NRES; j += 256) {
            float v = sD[j];
            if (v < best || (v == best && j < bidx)) { best = v; bidx = j; }
        }
        #pragma unroll
        for (int off = 16; off; off >>= 1) {
            float ov = __shfl_down_sync(0xffffffffu, best, off);
            int   oi = __shfl_down_sync(0xffffffffu, bidx, off);
            if (ov < best || (ov == best && oi < bidx)) { best = ov; bidx = oi; }
        }
        if (lane == 0) { sWv[warp] = best; sWi[warp] = bidx; }
        __syncthreads();
        if (tid == 0) {
            float bv = sWv[0]; int bi = sWi[0];
            #pragma unroll
            for (int w = 1; w < 8; w++) {
                float v = sWv[w]; int ii = sWi[w];
                if (v < bv || (v == bv && ii < bi)) { bv = v; bi = ii; }
            }
            g_eidx[(size_t)row * TOPK + sel] = bi;
            g_dn[(size_t)row * TOPK + sel] = bv;
            if (writeIdx) outIdxF[(size_t)row * TOPK + sel] = (float)bi;
            sD[bi] = INF;
        }
        __syncthreads();
    }
}

// ---------------- K3: edge features -> g_F ----------------
__device__ __forceinline__ void rbf16(float D, float* __restrict__ dst) {
    #pragma unroll
    for (int m = 0; m < NRBF; m++) {
        float mu = 2.0f + (20.0f / 15.0f) * (float)m;
        float t = (D - mu) * 0.8f;      // / 1.25
        dst[m] = __expf(-t * t);
    }
}

__global__ void __launch_bounds__(128) feat_kernel() {
    __shared__ float sAI[15];
    __shared__ float sAJ[TOPK * 15];
    __shared__ int   sJ[TOPK];
    __shared__ float sDn[TOPK];

    int row = blockIdx.x;
    int bq = row / NRES, i = row - bq * NRES;
    int tid = threadIdx.x;

    if (tid < TOPK) {
        sJ[tid] = g_eidx[(size_t)row * TOPK + tid];
        sDn[tid] = g_dn[(size_t)row * TOPK + tid];
    }
    if (tid < 15) sAI[tid] = g_atoms[(size_t)(bq * NRES + i) * 15 + tid];
    __syncthreads();
    for (int t = tid; t < TOPK * 15; t += 128) {
        int e = t / 15, r = t - e * 15;
        sAJ[t] = g_atoms[(size_t)(bq * NRES + sJ[e]) * 15 + r];
    }
    __syncthreads();

    float* Fr = g_F + (size_t)row * TOPK * EIN;
    for (int task = tid; task < 832; task += 128) {
        if (task < 768) {
            int p = task >> 5, e = task & 31;
            int ai = c_pa[p] * 3, bi = c_pb[p] * 3;
            float dx = sAI[ai + 0] - sAJ[e * 15 + bi + 0];
            float dy = sAI[ai + 1] - sAJ[e * 15 + bi + 1];
            float dz = sAI[ai + 2] - sAJ[e * 15 + bi + 2];
            float D = sqrtf(dx * dx + dy * dy + dz * dz + 1e-6f);
            rbf16(D, Fr + (size_t)e * EIN + 32 + p * 16);
        } else if (task < 800) {
            int e = task - 768;
            rbf16(sDn[e], Fr + (size_t)e * EIN + 16);
        } else {
            int e = task - 800;
            float d = (float)(sJ[e] - i);
            float* dst = Fr + (size_t)e * EIN;
            #pragma unroll
            for (int k = 0; k < 8; k++) {
                float s, c;
                sincosf(d * c_freq[k], &s, &c);
                dst[k] = c;
                dst[8 + k] = s;
            }
        }
    }
}

// ---------------- K4: 128x128 tiled fp32 GEMM (K=416) + fused LayerNorm ----------------
__global__ void __launch_bounds__(256) gemm_ln_kernel(const float* __restrict__ W,
                                                      const float* __restrict__ gamma,
                                                      const float* __restrict__ beta,
                                                      float* __restrict__ out) {
    __shared__ __align__(16) float sA[16][132];
    __shared__ __align__(16) float sB[16][132];

    int tile = blockIdx.x;
    int tid = threadIdx.x;
    int tx = tid & 15, ty = tid >> 4;
    size_t mBase = (size_t)tile * 128;

    float acc[8][8];
    #pragma unroll
    for (int r = 0; r < 8; r++)
        #pragma unroll
        for (int c = 0; c < 8; c++) acc[r][c] = 0.0f;

    for (int k0 = 0; k0 < EIN; k0 += 16) {
        #pragma unroll
        for (int j = 0; j < 2; j++) {
            int idx = tid + j * 256;
            int m = idx >> 2, kq = idx & 3;
            float4 v = *(const float4*)(g_F + (mBase + m) * EIN + k0 + kq * 4);
            sA[kq * 4 + 0][m] = v.x;
            sA[kq * 4 + 1][m] = v.y;
            sA[kq * 4 + 2][m] = v.z;
            sA[kq * 4 + 3][m] = v.w;
        }
        #pragma unroll
        for (int j = 0; j < 2; j++) {
            int idx = tid + j * 256;
            int kk = idx >> 5, nq = idx & 31;
            *(float4*)&sB[kk][nq * 4] = *(const float4*)(W + (size_t)(k0 + kk) * EFEAT + nq * 4);
        }
        __syncthreads();
        #pragma unroll
        for (int kk = 0; kk < 16; kk++) {
            float a[8], b[8];
            *(float4*)&a[0] = *(float4*)&sA[kk][ty * 4];
            *(float4*)&a[4] = *(float4*)&sA[kk][64 + ty * 4];
            *(float4*)&b[0] = *(float4*)&sB[kk][tx * 4];
            *(float4*)&b[4] = *(float4*)&sB[kk][64 + tx * 4];
            #pragma unroll
            for (int r = 0; r < 8; r++)
                #pragma unroll
                for (int c = 0; c < 8; c++)
                    acc[r][c] += a[r] * b[c];
        }
        __syncthreads();
    }

    float gam[8], bet[8];
    #pragma unroll
    for (int c = 0; c < 4; c++) {
        gam[c] = gamma[tx * 4 + c];
        gam[4 + c] = gamma[64 + tx * 4 + c];
        bet[c] = beta[tx * 4 + c];
        bet[4 + c] = beta[64 + tx * 4 + c];
    }

    #pragma unroll
    for (int r = 0; r < 8; r++) {
        float s = 0.0f;
        #pragma unroll
        for (int c = 0; c < 8; c++) s += acc[r][c];
        #pragma unroll
        for (int off = 8; off; off >>= 1) s += __shfl_xor_sync(0xffffffffu, s, off);
        float mu = s * (1.0f / 128.0f);
        float vs = 0.0f;
        #pragma unroll
        for (int c = 0; c < 8; c++) {
            float d = acc[r][c] - mu;
            vs += d * d;
        }
        #pragma unroll
        for (int off = 8; off; off >>= 1) vs += __shfl_xor_sync(0xffffffffu, vs, off);
        float var = vs * (1.0f / 128.0f);
        float inv = 1.0f / sqrtf(var + 1e-5f);

        int m = (r < 4) ? (ty * 4 + r) : (64 + ty * 4 + (r - 4));
        float o0[4], o1[4];
        #pragma unroll
        for (int c = 0; c < 4; c++) {
            o0[c] = (acc[r][c] - mu) * inv * gam[c] + bet[c];
            o1[c] = (acc[r][4 + c] - mu) * inv * gam[4 + c] + bet[4 + c];
        }
        float* op = out + (mBase + m) * EFEAT;
        *(float4*)(op + tx * 4) = *(float4*)o0;
        *(float4*)(op + 64 + tx * 4) = *(float4*)o1;
    }
}

// ---------------- launch ----------------
extern "C" void kernel_launch(void* const* d_in, const int* in_sizes, int n_in,
                              void* d_out, int out_size) {
    const float* X = (const float*)d_in[0];
    const float* mask = (const float*)d_in[1];
    const float* W = (const float*)d_in[2];
    const float* gamma = (const float*)d_in[3];
    const float* beta = (const float*)d_in[4];
    float* out = (float*)d_out;

    const int E_ELEMS = NEDGE * EFEAT;  // 33554432
    int writeIdx = (out_size >= E_ELEMS + NEDGE) ? 1 : 0;
    float* outIdx = out + E_ELEMS;

    atoms_kernel<<<(NROWS + 255) / 256, 256>>>(X);
    topk_kernel<<<NROWS, 256>>>(X, mask, outIdx, writeIdx);
    feat_kernel<<<NROWS, 128>>>();
    gemm_ln_kernel<<<NEDGE / 128, 256>>>(W, gamma, beta, out);
}

// round 3
// speedup vs baseline: 2.0503x; 2.0503x over previous
#include <cuda_runtime.h>
#include <cstdint>

#define BQ    4
#define NRES  2048
#define TOPK  32
#define NRBF  16
#define EIN   416
#define EFEAT 128
#define NROWS (BQ * NRES)          // 8192
#define NEDGE (NROWS * TOPK)       // 262144

// ---------------- device scratch (no allocs allowed) ----------------
__device__ float g_atoms[NROWS * 15];            // N,Ca,C,O,Cb xyz per residue
__device__ float g_dn[NEDGE];                    // top-k (adjusted) distances
__device__ int   g_eidx[NEDGE];                  // top-k indices (local j)

__constant__ int c_pa[24] = {0,2,3,4,1,1,1,1,0,0,0,4,4,3,0,2,3,4,2,3,4,2,3,2};
__constant__ int c_pb[24] = {0,2,3,4,0,2,3,4,2,3,4,2,3,2,1,1,1,1,0,0,0,4,4,3};
__constant__ float c_freq[8] = {
    1.0f, 0.31622776601683794f, 0.1f, 0.031622776601683794f,
    0.01f, 0.0031622776601683794f, 0.001f, 0.00031622776601683794f};

// ---------------- K1: per-residue atoms (N, Ca, C, O, virtual Cb) ----------------
__global__ void atoms_kernel(const float* __restrict__ X) {
    int r = blockIdx.x * blockDim.x + threadIdx.x;
    if (r >= NROWS) return;
    const float* x = X + (size_t)r * 12;
    float Nx = x[0], Ny = x[1], Nz = x[2];
    float Ax = x[3], Ay = x[4], Az = x[5];   // Ca
    float Cx = x[6], Cy = x[7], Cz = x[8];
    float Ox = x[9], Oy = x[10], Oz = x[11];
    float bx = Ax - Nx, by = Ay - Ny, bz = Az - Nz;
    float cx = Cx - Ax, cy = Cy - Ay, cz = Cz - Az;
    float ax = by * cz - bz * cy;
    float ay = bz * cx - bx * cz;
    float az = bx * cy - by * cx;
    float Bx = -0.58273431f * ax + 0.56802827f * bx - 0.54067466f * cx + Ax;
    float By = -0.58273431f * ay + 0.56802827f * by - 0.54067466f * cy + Ay;
    float Bz = -0.58273431f * az + 0.56802827f * bz - 0.54067466f * cz + Az;
    float* o = g_atoms + (size_t)r * 15;
    o[0] = Nx; o[1] = Ny; o[2] = Nz;
    o[3] = Ax; o[4] = Ay; o[5] = Az;
    o[6] = Cx; o[7] = Cy; o[8] = Cz;
    o[9] = Ox; o[10] = Oy; o[11] = Oz;
    o[12] = Bx; o[13] = By; o[14] = Bz;
}

// ---------------- K2: warp-per-row top-32 (no block barriers) ----------------
__global__ void __launch_bounds__(128) topk_kernel(const float* __restrict__ X,
                                                   const float* __restrict__ mask,
                                                   float* __restrict__ outIdxF,
                                                   int writeIdx) {
    __shared__ float sD[4][NRES];   // 32 KB

    int warp = threadIdx.x >> 5, lane = threadIdx.x & 31;
    int row = blockIdx.x * 4 + warp;
    int bq = row >> 11, i = row & (NRES - 1);
    const float* Xb = X + (size_t)bq * NRES * 12;
    const float* mb = mask + (size_t)bq * NRES;
    float* D = sD[warp];

    float cax = Xb[(size_t)i * 12 + 3];
    float cay = Xb[(size_t)i * 12 + 4];
    float caz = Xb[(size_t)i * 12 + 5];
    float mi = mb[i];

    float lmax = 0.0f;
    #pragma unroll 4
    for (int s = 0; s < NRES / 32; s++) {
        int j = lane + 32 * s;
        float dx = Xb[(size_t)j * 12 + 3] - cax;
        float dy = Xb[(size_t)j * 12 + 4] - cay;
        float dz = Xb[(size_t)j * 12 + 5] - caz;
        float d = sqrtf(dx * dx + dy * dy + dz * dz + 1e-6f);
        float dm = mi * mb[j] * d;
        D[j] = dm;
        lmax = fmaxf(lmax, dm);
    }
    #pragma unroll
    for (int off = 16; off; off >>= 1)
        lmax = fmaxf(lmax, __shfl_xor_sync(0xffffffffu, lmax, off));
    __syncwarp();
    #pragma unroll 4
    for (int s = 0; s < NRES / 32; s++) {
        int j = lane + 32 * s;
        float m2 = mi * mb[j];
        D[j] += (1.0f - m2) * lmax;
    }
    __syncwarp();

    const float INF = __int_as_float(0x7f800000);
    for (int sel = 0; sel < TOPK; sel++) {
        float best = INF;
        int bi = 0x7fffffff;
        #pragma unroll 8
        for (int s = 0; s < NRES / 32; s++) {
            int j = lane + 32 * s;
            float v = D[j];
            if (v < best) { best = v; bi = j; }
        }
        #pragma unroll
        for (int off = 16; off; off >>= 1) {
            float ov = __shfl_xor_sync(0xffffffffu, best, off);
            int   oi = __shfl_xor_sync(0xffffffffu, bi, off);
            if (ov < best || (ov == best && oi < bi)) { best = ov; bi = oi; }
        }
        if (lane == 0) {
            g_eidx[(size_t)row * TOPK + sel] = bi;
            g_dn[(size_t)row * TOPK + sel] = best;
            if (writeIdx) outIdxF[(size_t)row * TOPK + sel] = (float)bi;
        }
        if ((bi & 31) == lane) D[bi] = INF;
        __syncwarp();
    }
}

// ---------------- K3: fused features + 128x128 GEMM (K=416) + LayerNorm ----------------
__global__ void __launch_bounds__(256) gemm_ln_kernel(const float* __restrict__ W,
                                                      const float* __restrict__ gamma,
                                                      const float* __restrict__ beta,
                                                      float* __restrict__ out) {
    __shared__ __align__(16) float sA[16][132];
    __shared__ __align__(16) float sB[16][132];
    __shared__ __align__(16) float sPos[128][16];   // positional features
    __shared__ float sDist[128][25];                // 0: D_neighbor, 1..24: pair dists

    int tile = blockIdx.x;
    int tid = threadIdx.x;
    int tx = tid & 15, ty = tid >> 4;
    size_t mBase = (size_t)tile * 128;

    // ---- preamble: per-edge distances + positional features ----
    if (tid < 128) {
        int m = tid;
        int res = tile * 4 + (m >> 5);       // global residue row 0..8191
        int e = m & 31;
        int bq = res >> 11;
        int i = res & (NRES - 1);
        int j = g_eidx[(size_t)res * TOPK + e];
        sDist[m][0] = g_dn[(size_t)res * TOPK + e];

        const float* AI = g_atoms + (size_t)res * 15;
        const float* AJ = g_atoms + (size_t)(bq * NRES + j) * 15;
        float ai[15], aj[15];
        #pragma unroll
        for (int t = 0; t < 15; t++) { ai[t] = AI[t]; aj[t] = AJ[t]; }
        #pragma unroll
        for (int p = 0; p < 24; p++) {
            int a3 = c_pa[p] * 3, b3 = c_pb[p] * 3;
            float dx = ai[a3 + 0] - aj[b3 + 0];
            float dy = ai[a3 + 1] - aj[b3 + 1];
            float dz = ai[a3 + 2] - aj[b3 + 2];
            sDist[m][1 + p] = sqrtf(dx * dx + dy * dy + dz * dz + 1e-6f);
        }
        float d = (float)(j - i);
        #pragma unroll
        for (int k = 0; k < 8; k++) {
            float s, c;
            sincosf(d * c_freq[k], &s, &c);
            sPos[m][k] = c;
            sPos[m][8 + k] = s;
        }
    }

    float acc[8][8];
    #pragma unroll
    for (int r = 0; r < 8; r++)
        #pragma unroll
        for (int c = 0; c < 8; c++) acc[r][c] = 0.0f;

    __syncthreads();

    for (int k0 = 0; k0 < EIN; k0 += 16) {
        // ---- A tile: compute features on the fly ----
        if (k0 == 0) {
            #pragma unroll
            for (int j2 = 0; j2 < 2; j2++) {
                int idx = tid + j2 * 256;
                int m = idx >> 2, kq = idx & 3;
                float4 v = *(const float4*)&sPos[m][kq * 4];
                sA[kq * 4 + 0][m] = v.x;
                sA[kq * 4 + 1][m] = v.y;
                sA[kq * 4 + 2][m] = v.z;
                sA[kq * 4 + 3][m] = v.w;
            }
        } else {
            int g = (k0 - 16) >> 4;   // 0..24
            #pragma unroll
            for (int j2 = 0; j2 < 2; j2++) {
                int idx = tid + j2 * 256;
                int m = idx >> 2, kq = idx & 3;
                float Dv = sDist[m][g];
                #pragma unroll
                for (int c = 0; c < 4; c++) {
                    int mth = kq * 4 + c;
                    float t = (Dv - (2.0f + 1.3333333333f * (float)mth)) * 0.8f;
                    sA[mth][m] = __expf(-t * t);
                }
            }
        }
        // ---- B tile: W slab ----
        #pragma unroll
        for (int j2 = 0; j2 < 2; j2++) {
            int idx = tid + j2 * 256;
            int kk = idx >> 5, nq = idx & 31;
            *(float4*)&sB[kk][nq * 4] = *(const float4*)(W + (size_t)(k0 + kk) * EFEAT + nq * 4);
        }
        __syncthreads();
        #pragma unroll
        for (int kk = 0; kk < 16; kk++) {
            float a[8], b[8];
            *(float4*)&a[0] = *(float4*)&sA[kk][ty * 4];
            *(float4*)&a[4] = *(float4*)&sA[kk][64 + ty * 4];
            *(float4*)&b[0] = *(float4*)&sB[kk][tx * 4];
            *(float4*)&b[4] = *(float4*)&sB[kk][64 + tx * 4];
            #pragma unroll
            for (int r = 0; r < 8; r++)
                #pragma unroll
                for (int c = 0; c < 8; c++)
                    acc[r][c] += a[r] * b[c];
        }
        __syncthreads();
    }

    float gam[8], bet[8];
    #pragma unroll
    for (int c = 0; c < 4; c++) {
        gam[c] = gamma[tx * 4 + c];
        gam[4 + c] = gamma[64 + tx * 4 + c];
        bet[c] = beta[tx * 4 + c];
        bet[4 + c] = beta[64 + tx * 4 + c];
    }

    #pragma unroll
    for (int r = 0; r < 8; r++) {
        float s = 0.0f;
        #pragma unroll
        for (int c = 0; c < 8; c++) s += acc[r][c];
        #pragma unroll
        for (int off = 8; off; off >>= 1) s += __shfl_xor_sync(0xffffffffu, s, off);
        float mu = s * (1.0f / 128.0f);
        float vs = 0.0f;
        #pragma unroll
        for (int c = 0; c < 8; c++) {
            float d = acc[r][c] - mu;
            vs += d * d;
        }
        #pragma unroll
        for (int off = 8; off; off >>= 1) vs += __shfl_xor_sync(0xffffffffu, vs, off);
        float var = vs * (1.0f / 128.0f);
        float inv = 1.0f / sqrtf(var + 1e-5f);

        int m = (r < 4) ? (ty * 4 + r) : (64 + ty * 4 + (r - 4));
        float o0[4], o1[4];
        #pragma unroll
        for (int c = 0; c < 4; c++) {
            o0[c] = (acc[r][c] - mu) * inv * gam[c] + bet[c];
            o1[c] = (acc[r][4 + c] - mu) * inv * gam[4 + c] + bet[4 + c];
        }
        float* op = out + (mBase + m) * EFEAT;
        *(float4*)(op + tx * 4) = *(float4*)o0;
        *(float4*)(op + 64 + tx * 4) = *(float4*)o1;
    }
}

// ---------------- launch ----------------
extern "C" void kernel_launch(void* const* d_in, const int* in_sizes, int n_in,
                              void* d_out, int out_size) {
    const float* X = (const float*)d_in[0];
    const float* mask = (const float*)d_in[1];
    const float* W = (const float*)d_in[2];
    const float* gamma = (const float*)d_in[3];
    const float* beta = (const float*)d_in[4];
    float* out = (float*)d_out;

    const int E_ELEMS = NEDGE * EFEAT;  // 33554432
    int writeIdx = (out_size >= E_ELEMS + NEDGE) ? 1 : 0;
    float* outIdx = out + E_ELEMS;

    atoms_kernel<<<(NROWS + 255) / 256, 256>>>(X);
    topk_kernel<<<NROWS / 4, 128>>>(X, mask, outIdx, writeIdx);
    gemm_ln_kernel<<<NEDGE / 128, 256>>>(W, gamma, beta, out);
}

// round 6
// speedup vs baseline: 2.3791x; 1.1604x over previous
#include <cuda_runtime.h>
#include <cuda_bf16.h>
#include <cstdint>

#define NRES  2048
#define TOPK  32
#define EIN   416
#define NSTG  7            // 7 stages of 64 K-cols (448 padded)
#define EFEAT 128
#define NROWS 8192
#define NEDGE 262144

#define ASTRIDE 72         // bf16 elems per row (144 B) -> conflict-free frag loads
#define ABYTES  (128 * ASTRIDE * 2)     // 18432 per term
#define ESTRIDE 129        // fp32 epilogue stride

// ---------------- device scratch ----------------
__device__ float g_atoms[NROWS * 15];
__device__ float g_ca3[NROWS * 3];
__device__ float g_dn[NEDGE];
__device__ int   g_eidx[NEDGE];
__device__ __nv_bfloat16 g_Bhi[NSTG * 8192];   // [stage][n][64] bf16
__device__ __nv_bfloat16 g_Blo[NSTG * 8192];

__constant__ int c_pa[24] = {0,2,3,4,1,1,1,1,0,0,0,4,4,3,0,2,3,4,2,3,4,2,3,2};
__constant__ int c_pb[24] = {0,2,3,4,0,2,3,4,2,3,4,2,3,2,1,1,1,1,0,0,0,4,4,3};
__constant__ float c_freq[8] = {
    1.0f, 0.31622776601683794f, 0.1f, 0.031622776601683794f,
    0.01f, 0.0031622776601683794f, 0.001f, 0.00031622776601683794f};

__device__ __forceinline__ void mma16816(float* c, const uint32_t* a, uint32_t b0, uint32_t b1) {
    asm volatile("mma.sync.aligned.m16n8k16.row.col.f32.bf16.bf16.f32 "
                 "{%0,%1,%2,%3}, {%4,%5,%6,%7}, {%8,%9}, {%0,%1,%2,%3};"
                 : "+f"(c[0]), "+f"(c[1]), "+f"(c[2]), "+f"(c[3])
                 : "r"(a[0]), "r"(a[1]), "r"(a[2]), "r"(a[3]), "r"(b0), "r"(b1));
}

// ---------------- K1: per-residue atoms ----------------
__global__ void atoms_kernel(const float* __restrict__ X) {
    int r = blockIdx.x * blockDim.x + threadIdx.x;
    if (r >= NROWS) return;
    const float* x = X + (size_t)r * 12;
    float Nx = x[0], Ny = x[1], Nz = x[2];
    float Ax = x[3], Ay = x[4], Az = x[5];
    float Cx = x[6], Cy = x[7], Cz = x[8];
    float Ox = x[9], Oy = x[10], Oz = x[11];
    float bx = Ax - Nx, by = Ay - Ny, bz = Az - Nz;
    float cx = Cx - Ax, cy = Cy - Ay, cz = Cz - Az;
    float ax = by * cz - bz * cy;
    float ay = bz * cx - bx * cz;
    float az = bx * cy - by * cx;
    float Bx = -0.58273431f * ax + 0.56802827f * bx - 0.54067466f * cx + Ax;
    float By = -0.58273431f * ay + 0.56802827f * by - 0.54067466f * cy + Ay;
    float Bz = -0.58273431f * az + 0.56802827f * bz - 0.54067466f * cz + Az;
    float* o = g_atoms + (size_t)r * 15;
    o[0] = Nx; o[1] = Ny; o[2] = Nz;
    o[3] = Ax; o[4] = Ay; o[5] = Az;
    o[6] = Cx; o[7] = Cy; o[8] = Cz;
    o[9] = Ox; o[10] = Oy; o[11] = Oz;
    o[12] = Bx; o[13] = By; o[14] = Bz;
    g_ca3[(size_t)r * 3 + 0] = Ax;
    g_ca3[(size_t)r * 3 + 1] = Ay;
    g_ca3[(size_t)r * 3 + 2] = Az;
}

// ---------------- K2: W -> bf16 hi/lo stage images, [stage][n][64] ----------------
__global__ void prepw_kernel(const float* __restrict__ W) {
    int idx = blockIdx.x * blockDim.x + threadIdx.x;
    if (idx >= NSTG * 8192) return;
    int s = idx >> 13;
    int rem = idx & 8191;
    int n = rem >> 6;
    int c = rem & 63;
    int k = s * 64 + c;
    float v = (k < EIN) ? W[(size_t)k * EFEAT + n] : 0.0f;
    __nv_bfloat16 h = __float2bfloat16(v);
    float lo = v - __bfloat162float(h);
    g_Bhi[idx] = h;
    g_Blo[idx] = __float2bfloat16(lo);
}

// ---------------- K3: warp-per-row top-32 ----------------
__global__ void __launch_bounds__(128) topk_kernel(const float* __restrict__ mask,
                                                   float* __restrict__ outIdxF,
                                                   int writeIdx) {
    extern __shared__ float dynT[];
    float* sD = dynT;                // 4*2048
    float* sCa = dynT + 4 * NRES;    // 2048*3

    int tid = threadIdx.x;
    int warp = tid >> 5, lane = tid & 31;
    int row = blockIdx.x * 4 + warp;
    int bq = row >> 11, i = row & (NRES - 1);
    const float* mb = mask + (size_t)bq * NRES;
    float* D = sD + warp * NRES;

    for (int t = tid; t < NRES * 3; t += 128)
        sCa[t] = g_ca3[(size_t)bq * NRES * 3 + t];
    __syncthreads();

    float cax = sCa[i * 3 + 0];
    float cay = sCa[i * 3 + 1];
    float caz = sCa[i * 3 + 2];
    float mi = mb[i];

    float lmax = 0.0f;
    #pragma unroll 4
    for (int s = 0; s < NRES / 32; s++) {
        int j = lane + 32 * s;
        float dx = sCa[j * 3 + 0] - cax;
        float dy = sCa[j * 3 + 1] - cay;
        float dz = sCa[j * 3 + 2] - caz;
        float d = sqrtf(dx * dx + dy * dy + dz * dz + 1e-6f);
        float dm = mi * mb[j] * d;
        D[j] = dm;
        lmax = fmaxf(lmax, dm);
    }
    #pragma unroll
    for (int off = 16; off; off >>= 1)
        lmax = fmaxf(lmax, __shfl_xor_sync(0xffffffffu, lmax, off));
    __syncwarp();
    #pragma unroll 4
    for (int s = 0; s < NRES / 32; s++) {
        int j = lane + 32 * s;
        float m2 = mi * mb[j];
        D[j] += (1.0f - m2) * lmax;
    }
    __syncwarp();

    const float INF = __int_as_float(0x7f800000);
    for (int sel = 0; sel < TOPK; sel++) {
        float best = INF;
        int bi = 0x7fffffff;
        #pragma unroll 8
        for (int s = 0; s < NRES / 32; s++) {
            int j = lane + 32 * s;
            float v = D[j];
            if (v < best) { best = v; bi = j; }
        }
        #pragma unroll
        for (int off = 16; off; off >>= 1) {
            float ov = __shfl_xor_sync(0xffffffffu, best, off);
            int   oi = __shfl_xor_sync(0xffffffffu, bi, off);
            if (ov < best || (ov == best && oi < bi)) { best = ov; bi = oi; }
        }
        if (lane == 0) {
            g_eidx[(size_t)row * TOPK + sel] = bi;
            g_dn[(size_t)row * TOPK + sel] = best;
            if (writeIdx) outIdxF[(size_t)row * TOPK + sel] = (float)bi;
        }
        if ((bi & 31) == lane) D[bi] = INF;
        __syncwarp();
    }
}

// ---------------- K4: mma.sync bf16-split GEMM + LN ----------------
// CTA: 128 edges x 128 out, K = 7 stages of 64. 8 warps in 4(M) x 2(N).
__global__ void __launch_bounds__(256) gemm_mma_kernel(const float* __restrict__ gamma,
                                                       const float* __restrict__ beta,
                                                       float* __restrict__ out) {
    extern __shared__ char dyn[];
    __shared__ float sPos[128][16];
    __shared__ float sDist[128][25];
    __shared__ float sGam[128], sBet[128];
    __shared__ float sMu[128], sInv[128];

    char* Ah = dyn;                    // 128 x ASTRIDE bf16
    char* Al = dyn + ABYTES;
    char* Bh = dyn + 2 * ABYTES;       // 128(n) x ASTRIDE bf16
    char* Bl = dyn + 3 * ABYTES;
    float* E = (float*)dyn;            // reused in epilogue: 128 x ESTRIDE fp32

    int tile = blockIdx.x;
    int tid = threadIdx.x;
    int wid = tid >> 5, lane = tid & 31;
    int wm = wid >> 1, wn = wid & 1;

    // preamble: per-edge distances + positional + gamma/beta
    if (tid < 128) {
        sGam[tid] = gamma[tid];
        sBet[tid] = beta[tid];
        int m = tid;
        int res = tile * 4 + (m >> 5);
        int e = m & 31;
        int bq = res >> 11;
        int i = res & (NRES - 1);
        int j = g_eidx[(size_t)res * TOPK + e];
        sDist[m][0] = g_dn[(size_t)res * TOPK + e];
        const float* AI = g_atoms + (size_t)res * 15;
        const float* AJ = g_atoms + (size_t)(bq * NRES + j) * 15;
        float ai[15], aj[15];
        #pragma unroll
        for (int t = 0; t < 15; t++) { ai[t] = AI[t]; aj[t] = AJ[t]; }
        #pragma unroll
        for (int p = 0; p < 24; p++) {
            int a3 = c_pa[p] * 3, b3 = c_pb[p] * 3;
            float dx = ai[a3 + 0] - aj[b3 + 0];
            float dy = ai[a3 + 1] - aj[b3 + 1];
            float dz = ai[a3 + 2] - aj[b3 + 2];
            sDist[m][1 + p] = sqrtf(dx * dx + dy * dy + dz * dz + 1e-6f);
        }
        float d = (float)(j - i);
        #pragma unroll
        for (int k = 0; k < 8; k++) {
            float s, c;
            sincosf(d * c_freq[k], &s, &c);
            sPos[m][k] = c;
            sPos[m][8 + k] = s;
        }
    }

    float acc[2][8][4];
    #pragma unroll
    for (int mi = 0; mi < 2; mi++)
        #pragma unroll
        for (int ni = 0; ni < 8; ni++)
            #pragma unroll
            for (int q = 0; q < 4; q++) acc[mi][ni][q] = 0.0f;

    for (int s = 0; s < NSTG; s++) {
        __syncthreads();   // previous compute done (and preamble on s=0)

        // ---- A fill: 128 rows x 64 cols of features, bf16 hi/lo ----
        for (int t = tid; t < 1024; t += 256) {
            int m = t >> 3;
            int g = t & 7;
            int k0 = s * 64 + g * 8;
            float v[8];
            if (k0 < 16) {
                #pragma unroll
                for (int q = 0; q < 8; q++) v[q] = sPos[m][k0 + q];
            } else if (k0 >= EIN) {
                #pragma unroll
                for (int q = 0; q < 8; q++) v[q] = 0.0f;
            } else {
                float Dv = (k0 < 32) ? sDist[m][0] : sDist[m][1 + ((k0 - 32) >> 4)];
                #pragma unroll
                for (int q = 0; q < 8; q++) {
                    int mth = (k0 + q) & 15;
                    float tt = (Dv - (2.0f + 1.3333333333f * (float)mth)) * 0.8f;
                    v[q] = __expf(-tt * tt);
                }
            }
            uint32_t hp[4], lp[4];
            #pragma unroll
            for (int q = 0; q < 4; q++) {
                float v0 = v[2 * q], v1 = v[2 * q + 1];
                __nv_bfloat16 h0 = __float2bfloat16(v0);
                __nv_bfloat16 h1 = __float2bfloat16(v1);
                __nv_bfloat162 h2; h2.x = h0; h2.y = h1;
                __nv_bfloat162 l2 = __floats2bfloat162_rn(v0 - __bfloat162float(h0),
                                                          v1 - __bfloat162float(h1));
                hp[q] = *(uint32_t*)&h2;
                lp[q] = *(uint32_t*)&l2;
            }
            *(uint4*)(Ah + m * 144 + g * 16) = make_uint4(hp[0], hp[1], hp[2], hp[3]);
            *(uint4*)(Al + m * 144 + g * 16) = make_uint4(lp[0], lp[1], lp[2], lp[3]);
        }
        // ---- B fill: copy stage image with stride padding ----
        {
            const uint32_t* srcH = (const uint32_t*)(g_Bhi + s * 8192);
            const uint32_t* srcL = (const uint32_t*)(g_Blo + s * 8192);
            for (int t = tid; t < 4096; t += 256) {
                int n = t >> 5, kp = t & 31;
                ((uint32_t*)Bh)[n * 36 + kp] = srcH[t];
                ((uint32_t*)Bl)[n * 36 + kp] = srcL[t];
            }
        }
        __syncthreads();

        // ---- compute: 4 k16-steps ----
        #pragma unroll
        for (int ks = 0; ks < 4; ks++) {
            uint32_t ahi[2][4], alo[2][4];
            #pragma unroll
            for (int mi = 0; mi < 2; mi++) {
                int rb = (wm * 32 + mi * 16 + (lane >> 2)) * 144 + ks * 32 + (lane & 3) * 4;
                ahi[mi][0] = *(const uint32_t*)(Ah + rb);
                ahi[mi][1] = *(const uint32_t*)(Ah + rb + 8 * 144);
                ahi[mi][2] = *(const uint32_t*)(Ah + rb + 16);
                ahi[mi][3] = *(const uint32_t*)(Ah + rb + 8 * 144 + 16);
                alo[mi][0] = *(const uint32_t*)(Al + rb);
                alo[mi][1] = *(const uint32_t*)(Al + rb + 8 * 144);
                alo[mi][2] = *(const uint32_t*)(Al + rb + 16);
                alo[mi][3] = *(const uint32_t*)(Al + rb + 8 * 144 + 16);
            }
            #pragma unroll
            for (int ni = 0; ni < 8; ni++) {
                int cb = (wn * 64 + ni * 8 + (lane >> 2)) * 144 + ks * 32 + (lane & 3) * 4;
                uint32_t bh0 = *(const uint32_t*)(Bh + cb);
                uint32_t bh1 = *(const uint32_t*)(Bh + cb + 16);
                uint32_t bl0 = *(const uint32_t*)(Bl + cb);
                uint32_t bl1 = *(const uint32_t*)(Bl + cb + 16);
                #pragma unroll
                for (int mi = 0; mi < 2; mi++) {
                    mma16816(acc[mi][ni], ahi[mi], bh0, bh1);
                    mma16816(acc[mi][ni], ahi[mi], bl0, bl1);
                    mma16816(acc[mi][ni], alo[mi], bh0, bh1);
                }
            }
        }
    }

    // ---- epilogue: dump accums to smem, per-row LayerNorm, store ----
    __syncthreads();
    #pragma unroll
    for (int mi = 0; mi < 2; mi++) {
        int r0 = wm * 32 + mi * 16 + (lane >> 2);
        #pragma unroll
        for (int ni = 0; ni < 8; ni++) {
            int c0 = wn * 64 + ni * 8 + (lane & 3) * 2;
            E[r0 * ESTRIDE + c0] = acc[mi][ni][0];
            E[r0 * ESTRIDE + c0 + 1] = acc[mi][ni][1];
            E[(r0 + 8) * ESTRIDE + c0] = acc[mi][ni][2];
            E[(r0 + 8) * ESTRIDE + c0 + 1] = acc[mi][ni][3];
        }
    }
    __syncthreads();

    if (tid < 128) {
        int r = tid;
        float sum = 0.0f, sq = 0.0f;
        #pragma unroll 16
        for (int c = 0; c < 128; c++) {
            float v = E[r * ESTRIDE + c];
            sum += v;
            sq += v * v;
        }
        float mu = sum * (1.0f / 128.0f);
        float var = sq * (1.0f / 128.0f) - mu * mu;
        sMu[r] = mu;
        sInv[r] = rsqrtf(fmaxf(var, 0.0f) + 1e-5f);
    }
    __syncthreads();

    for (int t = tid; t < 128 * 32; t += 256) {
        int m = t >> 5, q = t & 31;
        float mu = sMu[m], inv = sInv[m];
        float o0 = (E[m * ESTRIDE + q * 4 + 0] - mu) * inv * sGam[q * 4 + 0] + sBet[q * 4 + 0];
        float o1 = (E[m * ESTRIDE + q * 4 + 1] - mu) * inv * sGam[q * 4 + 1] + sBet[q * 4 + 1];
        float o2 = (E[m * ESTRIDE + q * 4 + 2] - mu) * inv * sGam[q * 4 + 2] + sBet[q * 4 + 2];
        float o3 = (E[m * ESTRIDE + q * 4 + 3] - mu) * inv * sGam[q * 4 + 3] + sBet[q * 4 + 3];
        float4 o = make_float4(o0, o1, o2, o3);
        *(float4*)(out + ((size_t)tile * 128 + m) * EFEAT + q * 4) = o;
    }
}

// ---------------- launch ----------------
extern "C" void kernel_launch(void* const* d_in, const int* in_sizes, int n_in,
                              void* d_out, int out_size) {
    const float* X = (const float*)d_in[0];
    const float* mask = (const float*)d_in[1];
    const float* W = (const float*)d_in[2];
    const float* gamma = (const float*)d_in[3];
    const float* beta = (const float*)d_in[4];
    float* out = (float*)d_out;

    const int E_ELEMS = NEDGE * EFEAT;
    int writeIdx = (out_size >= E_ELEMS + NEDGE) ? 1 : 0;
    float* outIdx = out + E_ELEMS;

    const int DYN = 4 * ABYTES;   // 73728; epilogue E (66048) fits inside
    cudaFuncSetAttribute(topk_kernel, cudaFuncAttributeMaxDynamicSharedMemorySize, 57344);
    cudaFuncSetAttribute(gemm_mma_kernel, cudaFuncAttributeMaxDynamicSharedMemorySize, DYN);

    atoms_kernel<<<(NROWS + 255) / 256, 256>>>(X);
    prepw_kernel<<<(NSTG * 8192 + 255) / 256, 256>>>(W);
    topk_kernel<<<NROWS / 4, 128, 57344>>>(mask, outIdx, writeIdx);
    gemm_mma_kernel<<<NEDGE / 128, 256, DYN>>>(gamma, beta, out);
}

// round 9
// speedup vs baseline: 3.0011x; 1.2614x over previous
#include <cuda_runtime.h>
#include <cuda_bf16.h>
#include <cstdint>

#define NRES  2048
#define TOPK  32
#define EIN   416
#define NSTG  7            // 7 stages of 64 K-cols (448 padded)
#define EFEAT 128
#define NROWS 8192
#define NEDGE 262144

#define ASTRIDE 72         // bf16 elems per row (144 B) -> conflict-free frag loads
#define ABYTES  (128 * ASTRIDE * 2)     // 18432 per term
#define ESTRIDE 129        // fp32 epilogue stride

// ---------------- device scratch ----------------
__device__ float g_atoms[NROWS * 15];
__device__ float g_ca3[NROWS * 3];
__device__ float g_dn[NEDGE];
__device__ int   g_eidx[NEDGE];
__device__ __nv_bfloat16 g_Bhi[NSTG * 8192];   // [stage][n][64] bf16
__device__ __nv_bfloat16 g_Blo[NSTG * 8192];

__constant__ int c_pa[24] = {0,2,3,4,1,1,1,1,0,0,0,4,4,3,0,2,3,4,2,3,4,2,3,2};
__constant__ int c_pb[24] = {0,2,3,4,0,2,3,4,2,3,4,2,3,2,1,1,1,1,0,0,0,4,4,3};
__constant__ float c_freq[8] = {
    1.0f, 0.31622776601683794f, 0.1f, 0.031622776601683794f,
    0.01f, 0.0031622776601683794f, 0.001f, 0.00031622776601683794f};

__device__ __forceinline__ void mma16816(float* c, const uint32_t* a, uint32_t b0, uint32_t b1) {
    asm volatile("mma.sync.aligned.m16n8k16.row.col.f32.bf16.bf16.f32 "
                 "{%0,%1,%2,%3}, {%4,%5,%6,%7}, {%8,%9}, {%0,%1,%2,%3};"
                 : "+f"(c[0]), "+f"(c[1]), "+f"(c[2]), "+f"(c[3])
                 : "r"(a[0]), "r"(a[1]), "r"(a[2]), "r"(a[3]), "r"(b0), "r"(b1));
}

// ---------------- K1: per-residue atoms ----------------
__global__ void atoms_kernel(const float* __restrict__ X) {
    int r = blockIdx.x * blockDim.x + threadIdx.x;
    if (r >= NROWS) return;
    const float* x = X + (size_t)r * 12;
    float Nx = x[0], Ny = x[1], Nz = x[2];
    float Ax = x[3], Ay = x[4], Az = x[5];
    float Cx = x[6], Cy = x[7], Cz = x[8];
    float Ox = x[9], Oy = x[10], Oz = x[11];
    float bx = Ax - Nx, by = Ay - Ny, bz = Az - Nz;
    float cx = Cx - Ax, cy = Cy - Ay, cz = Cz - Az;
    float ax = by * cz - bz * cy;
    float ay = bz * cx - bx * cz;
    float az = bx * cy - by * cx;
    float Bx = -0.58273431f * ax + 0.56802827f * bx - 0.54067466f * cx + Ax;
    float By = -0.58273431f * ay + 0.56802827f * by - 0.54067466f * cy + Ay;
    float Bz = -0.58273431f * az + 0.56802827f * bz - 0.54067466f * cz + Az;
    float* o = g_atoms + (size_t)r * 15;
    o[0] = Nx; o[1] = Ny; o[2] = Nz;
    o[3] = Ax; o[4] = Ay; o[5] = Az;
    o[6] = Cx; o[7] = Cy; o[8] = Cz;
    o[9] = Ox; o[10] = Oy; o[11] = Oz;
    o[12] = Bx; o[13] = By; o[14] = Bz;
    g_ca3[(size_t)r * 3 + 0] = Ax;
    g_ca3[(size_t)r * 3 + 1] = Ay;
    g_ca3[(size_t)r * 3 + 2] = Az;
}

// ---------------- K2: W -> bf16 hi/lo stage images, [stage][n][64] ----------------
__global__ void prepw_kernel(const float* __restrict__ W) {
    int idx = blockIdx.x * blockDim.x + threadIdx.x;
    if (idx >= NSTG * 8192) return;
    int s = idx >> 13;
    int rem = idx & 8191;
    int n = rem >> 6;
    int c = rem & 63;
    int k = s * 64 + c;
    float v = (k < EIN) ? W[(size_t)k * EFEAT + n] : 0.0f;
    __nv_bfloat16 h = __float2bfloat16(v);
    float lo = v - __bfloat162float(h);
    g_Bhi[idx] = h;
    g_Blo[idx] = __float2bfloat16(lo);
}

// ---------------- K3: warp-per-row top-32 ----------------
__global__ void __launch_bounds__(128) topk_kernel(const float* __restrict__ mask,
                                                   float* __restrict__ outIdxF,
                                                   int writeIdx) {
    extern __shared__ float dynT[];
    float* sD = dynT;                 // 4*2048
    float* sCa = dynT + 4 * NRES;     // 2048*3
    float* sM = dynT + 7 * NRES;      // 2048

    int tid = threadIdx.x;
    int warp = tid >> 5, lane = tid & 31;
    int row = blockIdx.x * 4 + warp;
    int bq = row >> 11, i = row & (NRES - 1);
    float* D = sD + warp * NRES;

    for (int t = tid; t < NRES * 3; t += 128)
        sCa[t] = g_ca3[(size_t)bq * NRES * 3 + t];
    for (int t = tid; t < NRES; t += 128)
        sM[t] = mask[(size_t)bq * NRES + t];
    __syncthreads();

    float cax = sCa[i * 3 + 0];
    float cay = sCa[i * 3 + 1];
    float caz = sCa[i * 3 + 2];
    float mi = sM[i];

    float lmax = 0.0f;
    #pragma unroll 4
    for (int s = 0; s < NRES / 32; s++) {
        int j = lane + 32 * s;
        float dx = sCa[j * 3 + 0] - cax;
        float dy = sCa[j * 3 + 1] - cay;
        float dz = sCa[j * 3 + 2] - caz;
        float d = sqrtf(dx * dx + dy * dy + dz * dz + 1e-6f);
        float dm = mi * sM[j] * d;
        D[j] = dm;
        lmax = fmaxf(lmax, dm);
    }
    #pragma unroll
    for (int off = 16; off; off >>= 1)
        lmax = fmaxf(lmax, __shfl_xor_sync(0xffffffffu, lmax, off));
    __syncwarp();
    #pragma unroll 4
    for (int s = 0; s < NRES / 32; s++) {
        int j = lane + 32 * s;
        float m2 = mi * sM[j];
        D[j] += (1.0f - m2) * lmax;
    }
    __syncwarp();

    const float INF = __int_as_float(0x7f800000);
    for (int sel = 0; sel < TOPK; sel++) {
        float best = INF;
        int bi = 0x7fffffff;
        #pragma unroll 8
        for (int s = 0; s < NRES / 32; s++) {
            int j = lane + 32 * s;
            float v = D[j];
            if (v < best) { best = v; bi = j; }
        }
        #pragma unroll
        for (int off = 16; off; off >>= 1) {
            float ov = __shfl_xor_sync(0xffffffffu, best, off);
            int   oi = __shfl_xor_sync(0xffffffffu, bi, off);
            if (ov < best || (ov == best && oi < bi)) { best = ov; bi = oi; }
        }
        if (lane == 0) {
            g_eidx[(size_t)row * TOPK + sel] = bi;
            g_dn[(size_t)row * TOPK + sel] = best;
            if (writeIdx) outIdxF[(size_t)row * TOPK + sel] = (float)bi;
        }
        if ((bi & 31) == lane) D[bi] = INF;
        __syncwarp();
    }
}

// ---------------- K4: mma.sync bf16-split GEMM + LN, 2 CTAs/SM ----------------
__global__ void __launch_bounds__(256, 2) gemm_mma_kernel(const float* __restrict__ gamma,
                                                          const float* __restrict__ beta,
                                                          float* __restrict__ out) {
    extern __shared__ char dyn[];
    __shared__ float sPos[128][16];
    __shared__ float sDist[128][25];
    __shared__ float sGam[128], sBet[128];
    __shared__ float sMu[128], sInv[128];

    char* Ah = dyn;                    // 128 x ASTRIDE bf16
    char* Al = dyn + ABYTES;
    char* Bh = dyn + 2 * ABYTES;       // 128(n) x ASTRIDE bf16
    char* Bl = dyn + 3 * ABYTES;
    float* E = (float*)dyn;            // epilogue reuse: 128 x ESTRIDE fp32

    int tile = blockIdx.x;
    int tid = threadIdx.x;
    int wid = tid >> 5, lane = tid & 31;
    int wm = wid >> 1, wn = wid & 1;

    // preamble
    if (tid < 128) {
        sGam[tid] = gamma[tid];
        sBet[tid] = beta[tid];
        int m = tid;
        int res = tile * 4 + (m >> 5);
        int e = m & 31;
        int bq = res >> 11;
        int i = res & (NRES - 1);
        int j = g_eidx[(size_t)res * TOPK + e];
        sDist[m][0] = g_dn[(size_t)res * TOPK + e];
        const float* AI = g_atoms + (size_t)res * 15;
        const float* AJ = g_atoms + (size_t)(bq * NRES + j) * 15;
        float ai[15], aj[15];
        #pragma unroll
        for (int t = 0; t < 15; t++) { ai[t] = AI[t]; aj[t] = AJ[t]; }
        #pragma unroll
        for (int p = 0; p < 24; p++) {
            int a3 = c_pa[p] * 3, b3 = c_pb[p] * 3;
            float dx = ai[a3 + 0] - aj[b3 + 0];
            float dy = ai[a3 + 1] - aj[b3 + 1];
            float dz = ai[a3 + 2] - aj[b3 + 2];
            sDist[m][1 + p] = sqrtf(dx * dx + dy * dy + dz * dz + 1e-6f);
        }
        float d = (float)(j - i);
        #pragma unroll
        for (int k = 0; k < 8; k++) {
            float s, c;
            sincosf(d * c_freq[k], &s, &c);
            sPos[m][k] = c;
            sPos[m][8 + k] = s;
        }
    }

    float acc[2][8][4];
    #pragma unroll
    for (int mi = 0; mi < 2; mi++)
        #pragma unroll
        for (int ni = 0; ni < 8; ni++)
            #pragma unroll
            for (int q = 0; q < 4; q++) acc[mi][ni][q] = 0.0f;

    for (int s = 0; s < NSTG; s++) {
        __syncthreads();   // prior compute done (and preamble on s=0)

        // ---- A fill: 128 rows x 64 cols of features, bf16 hi/lo ----
        for (int t = tid; t < 1024; t += 256) {
            int m = t >> 3;
            int g = t & 7;
            int k0 = s * 64 + g * 8;
            float v[8];
            if (k0 < 16) {
                #pragma unroll
                for (int q = 0; q < 8; q++) v[q] = sPos[m][k0 + q];
            } else if (k0 >= EIN) {
                #pragma unroll
                for (int q = 0; q < 8; q++) v[q] = 0.0f;
            } else {
                float Dv = (k0 < 32) ? sDist[m][0] : sDist[m][1 + ((k0 - 32) >> 4)];
                #pragma unroll
                for (int q = 0; q < 8; q++) {
                    int mth = (k0 + q) & 15;
                    float tt = (Dv - (2.0f + 1.3333333333f * (float)mth)) * 0.8f;
                    v[q] = __expf(-tt * tt);
                }
            }
            uint32_t hp[4], lp[4];
            #pragma unroll
            for (int q = 0; q < 4; q++) {
                float v0 = v[2 * q], v1 = v[2 * q + 1];
                __nv_bfloat16 h0 = __float2bfloat16(v0);
                __nv_bfloat16 h1 = __float2bfloat16(v1);
                __nv_bfloat162 h2; h2.x = h0; h2.y = h1;
                __nv_bfloat162 l2 = __floats2bfloat162_rn(v0 - __bfloat162float(h0),
                                                          v1 - __bfloat162float(h1));
                hp[q] = *(uint32_t*)&h2;
                lp[q] = *(uint32_t*)&l2;
            }
            *(uint4*)(Ah + m * 144 + g * 16) = make_uint4(hp[0], hp[1], hp[2], hp[3]);
            *(uint4*)(Al + m * 144 + g * 16) = make_uint4(lp[0], lp[1], lp[2], lp[3]);
        }
        // ---- B fill: copy stage image with stride padding ----
        {
            const uint32_t* srcH = (const uint32_t*)(g_Bhi + s * 8192);
            const uint32_t* srcL = (const uint32_t*)(g_Blo + s * 8192);
            for (int t = tid; t < 4096; t += 256) {
                int n = t >> 5, kp = t & 31;
                ((uint32_t*)Bh)[n * 36 + kp] = srcH[t];
                ((uint32_t*)Bl)[n * 36 + kp] = srcL[t];
            }
        }
        __syncthreads();

        // ---- compute: 4 k16-steps ----
        #pragma unroll
        for (int ks = 0; ks < 4; ks++) {
            uint32_t ahi[2][4], alo[2][4];
            #pragma unroll
            for (int mi = 0; mi < 2; mi++) {
                int rb = (wm * 32 + mi * 16 + (lane >> 2)) * 144 + ks * 32 + (lane & 3) * 4;
                ahi[mi][0] = *(const uint32_t*)(Ah + rb);
                ahi[mi][1] = *(const uint32_t*)(Ah + rb + 8 * 144);
                ahi[mi][2] = *(const uint32_t*)(Ah + rb + 16);
                ahi[mi][3] = *(const uint32_t*)(Ah + rb + 8 * 144 + 16);
                alo[mi][0] = *(const uint32_t*)(Al + rb);
                alo[mi][1] = *(const uint32_t*)(Al + rb + 8 * 144);
                alo[mi][2] = *(const uint32_t*)(Al + rb + 16);
                alo[mi][3] = *(const uint32_t*)(Al + rb + 8 * 144 + 16);
            }
            #pragma unroll
            for (int ni = 0; ni < 8; ni++) {
                int cb = (wn * 64 + ni * 8 + (lane >> 2)) * 144 + ks * 32 + (lane & 3) * 4;
                uint32_t bh0 = *(const uint32_t*)(Bh + cb);
                uint32_t bh1 = *(const uint32_t*)(Bh + cb + 16);
                uint32_t bl0 = *(const uint32_t*)(Bl + cb);
                uint32_t bl1 = *(const uint32_t*)(Bl + cb + 16);
                #pragma unroll
                for (int mi = 0; mi < 2; mi++) {
                    mma16816(acc[mi][ni], ahi[mi], bh0, bh1);
                    mma16816(acc[mi][ni], ahi[mi], bl0, bl1);
                    mma16816(acc[mi][ni], alo[mi], bh0, bh1);
                }
            }
        }
    }

    // ---- epilogue ----
    __syncthreads();
    #pragma unroll
    for (int mi = 0; mi < 2; mi++) {
        int r0 = wm * 32 + mi * 16 + (lane >> 2);
        #pragma unroll
        for (int ni = 0; ni < 8; ni++) {
            int c0 = wn * 64 + ni * 8 + (lane & 3) * 2;
            E[r0 * ESTRIDE + c0] = acc[mi][ni][0];
            E[r0 * ESTRIDE + c0 + 1] = acc[mi][ni][1];
            E[(r0 + 8) * ESTRIDE + c0] = acc[mi][ni][2];
            E[(r0 + 8) * ESTRIDE + c0 + 1] = acc[mi][ni][3];
        }
    }
    __syncthreads();

    if (tid < 128) {
        int r = tid;
        float sum = 0.0f, sq = 0.0f;
        #pragma unroll 16
        for (int c = 0; c < 128; c++) {
            float v = E[r * ESTRIDE + c];
            sum += v;
            sq += v * v;
        }
        float mu = sum * (1.0f / 128.0f);
        float var = sq * (1.0f / 128.0f) - mu * mu;
        sMu[r] = mu;
        sInv[r] = rsqrtf(fmaxf(var, 0.0f) + 1e-5f);
    }
    __syncthreads();

    for (int t = tid; t < 128 * 32; t += 256) {
        int m = t >> 5, q = t & 31;
        float mu = sMu[m], inv = sInv[m];
        float o0 = (E[m * ESTRIDE + q * 4 + 0] - mu) * inv * sGam[q * 4 + 0] + sBet[q * 4 + 0];
        float o1 = (E[m * ESTRIDE + q * 4 + 1] - mu) * inv * sGam[q * 4 + 1] + sBet[q * 4 + 1];
        float o2 = (E[m * ESTRIDE + q * 4 + 2] - mu) * inv * sGam[q * 4 + 2] + sBet[q * 4 + 2];
        float o3 = (E[m * ESTRIDE + q * 4 + 3] - mu) * inv * sGam[q * 4 + 3] + sBet[q * 4 + 3];
        float4 o = make_float4(o0, o1, o2, o3);
        *(float4*)(out + ((size_t)tile * 128 + m) * EFEAT + q * 4) = o;
    }
}

// ---------------- launch ----------------
extern "C" void kernel_launch(void* const* d_in, const int* in_sizes, int n_in,
                              void* d_out, int out_size) {
    const float* X = (const float*)d_in[0];
    const float* mask = (const float*)d_in[1];
    const float* W = (const float*)d_in[2];
    const float* gamma = (const float*)d_in[3];
    const float* beta = (const float*)d_in[4];
    float* out = (float*)d_out;

    const int E_ELEMS = NEDGE * EFEAT;
    int writeIdx = (out_size >= E_ELEMS + NEDGE) ? 1 : 0;
    float* outIdx = out + E_ELEMS;

    const int DYN = 4 * ABYTES;   // 73728
    cudaFuncSetAttribute(topk_kernel, cudaFuncAttributeMaxDynamicSharedMemorySize, 65536);
    cudaFuncSetAttribute(gemm_mma_kernel, cudaFuncAttributeMaxDynamicSharedMemorySize, DYN);

    atoms_kernel<<<(NROWS + 255) / 256, 256>>>(X);
    prepw_kernel<<<(NSTG * 8192 + 255) / 256, 256>>>(W);
    topk_kernel<<<NROWS / 4, 128, 65536>>>(mask, outIdx, writeIdx);
    gemm_mma_kernel<<<NEDGE / 128, 256, DYN>>>(gamma, beta, out);
}

// round 12
// speedup vs baseline: 3.6877x; 1.2288x over previous
#include <cuda_runtime.h>
#include <cuda_bf16.h>
#include <cstdint>

#define NRES  2048
#define TOPK  32
#define EIN   416
#define NSTG  7            // 7 stages of 64 K-cols (448 padded)
#define EFEAT 128
#define NROWS 8192
#define NEDGE 262144

#define ASTRIDE 72         // bf16 elems per row (144 B)
#define ABYTES  (128 * ASTRIDE * 2)     // 18432 per term
#define ESTRIDE 129        // fp32 epilogue stride

// ---------------- device scratch ----------------
__device__ float g_atoms[NROWS * 15];
__device__ float g_ca3[NROWS * 3];
__device__ float g_dn[NEDGE];
__device__ int   g_eidx[NEDGE];
__device__ __nv_bfloat16 g_Bhi[NSTG * 8192];   // [stage][n][64] bf16
__device__ __nv_bfloat16 g_Blo[NSTG * 8192];

__constant__ int c_pa[24] = {0,2,3,4,1,1,1,1,0,0,0,4,4,3,0,2,3,4,2,3,4,2,3,2};
__constant__ int c_pb[24] = {0,2,3,4,0,2,3,4,2,3,4,2,3,2,1,1,1,1,0,0,0,4,4,3};
__constant__ float c_freq[8] = {
    1.0f, 0.31622776601683794f, 0.1f, 0.031622776601683794f,
    0.01f, 0.0031622776601683794f, 0.001f, 0.00031622776601683794f};

__device__ __forceinline__ void mma16816(float* c, const uint32_t* a, uint32_t b0, uint32_t b1) {
    asm volatile("mma.sync.aligned.m16n8k16.row.col.f32.bf16.bf16.f32 "
                 "{%0,%1,%2,%3}, {%4,%5,%6,%7}, {%8,%9}, {%0,%1,%2,%3};"
                 : "+f"(c[0]), "+f"(c[1]), "+f"(c[2]), "+f"(c[3])
                 : "r"(a[0]), "r"(a[1]), "r"(a[2]), "r"(a[3]), "r"(b0), "r"(b1));
}

// ---------------- K1: per-residue atoms ----------------
__global__ void atoms_kernel(const float* __restrict__ X) {
    int r = blockIdx.x * blockDim.x + threadIdx.x;
    if (r >= NROWS) return;
    const float* x = X + (size_t)r * 12;
    float Nx = x[0], Ny = x[1], Nz = x[2];
    float Ax = x[3], Ay = x[4], Az = x[5];
    float Cx = x[6], Cy = x[7], Cz = x[8];
    float Ox = x[9], Oy = x[10], Oz = x[11];
    float bx = Ax - Nx, by = Ay - Ny, bz = Az - Nz;
    float cx = Cx - Ax, cy = Cy - Ay, cz = Cz - Az;
    float ax = by * cz - bz * cy;
    float ay = bz * cx - bx * cz;
    float az = bx * cy - by * cx;
    float Bx = -0.58273431f * ax + 0.56802827f * bx - 0.54067466f * cx + Ax;
    float By = -0.58273431f * ay + 0.56802827f * by - 0.54067466f * cy + Ay;
    float Bz = -0.58273431f * az + 0.56802827f * bz - 0.54067466f * cz + Az;
    float* o = g_atoms + (size_t)r * 15;
    o[0] = Nx; o[1] = Ny; o[2] = Nz;
    o[3] = Ax; o[4] = Ay; o[5] = Az;
    o[6] = Cx; o[7] = Cy; o[8] = Cz;
    o[9] = Ox; o[10] = Oy; o[11] = Oz;
    o[12] = Bx; o[13] = By; o[14] = Bz;
    g_ca3[(size_t)r * 3 + 0] = Ax;
    g_ca3[(size_t)r * 3 + 1] = Ay;
    g_ca3[(size_t)r * 3 + 2] = Az;
}

// ---------------- K2: W -> bf16 hi/lo stage images, [stage][n][64] ----------------
__global__ void prepw_kernel(const float* __restrict__ W) {
    int idx = blockIdx.x * blockDim.x + threadIdx.x;
    if (idx >= NSTG * 8192) return;
    int s = idx >> 13;
    int rem = idx & 8191;
    int n = rem >> 6;
    int c = rem & 63;
    int k = s * 64 + c;
    float v = (k < EIN) ? W[(size_t)k * EFEAT + n] : 0.0f;
    __nv_bfloat16 h = __float2bfloat16(v);
    float lo = v - __bfloat162float(h);
    g_Bhi[idx] = h;
    g_Blo[idx] = __float2bfloat16(lo);
}

// ---------------- K3: warp-per-row top-32, tournament + segment rescan ----------------
__global__ void __launch_bounds__(256) topk_kernel(const float* __restrict__ mask,
                                                   float* __restrict__ outIdxF,
                                                   int writeIdx) {
    extern __shared__ float dynT[];
    float* sD = dynT;                 // 8 * 2048
    float* sCa = dynT + 8 * NRES;     // 2048 * 3
    float* sM = dynT + 11 * NRES;     // 2048

    int tid = threadIdx.x;
    int warp = tid >> 5, lane = tid & 31;
    int row = blockIdx.x * 8 + warp;
    int bq = row >> 11, i = row & (NRES - 1);
    float* D = sD + warp * NRES;

    for (int t = tid; t < NRES * 3; t += 256)
        sCa[t] = g_ca3[(size_t)bq * NRES * 3 + t];
    for (int t = tid; t < NRES; t += 256)
        sM[t] = mask[(size_t)bq * NRES + t];
    __syncthreads();

    float cax = sCa[i * 3 + 0];
    float cay = sCa[i * 3 + 1];
    float caz = sCa[i * 3 + 2];
    float mi = sM[i];

    float lmax = 0.0f;
    #pragma unroll 4
    for (int s = 0; s < NRES / 32; s++) {
        int j = lane + 32 * s;
        float dx = sCa[j * 3 + 0] - cax;
        float dy = sCa[j * 3 + 1] - cay;
        float dz = sCa[j * 3 + 2] - caz;
        float d = sqrtf(dx * dx + dy * dy + dz * dz + 1e-6f);
        float dm = mi * sM[j] * d;
        D[j] = dm;
        lmax = fmaxf(lmax, dm);
    }
    #pragma unroll
    for (int off = 16; off; off >>= 1)
        lmax = fmaxf(lmax, __shfl_xor_sync(0xffffffffu, lmax, off));
    __syncwarp();
    #pragma unroll 4
    for (int s = 0; s < NRES / 32; s++) {
        int j = lane + 32 * s;
        float m2 = mi * sM[j];
        D[j] += (1.0f - m2) * lmax;
    }
    __syncwarp();

    const float INF = __int_as_float(0x7f800000);

    // per-lane segment min: lane l owns D[64l .. 64l+63]
    float bv = INF;
    int bidx = 0x7fffffff;
    #pragma unroll 8
    for (int t = 0; t < 64; t++) {
        int idx = (lane << 6) + ((t + lane) & 63);   // rotated: conflict-free
        float v = D[idx];
        if (v < bv || (v == bv && idx < bidx)) { bv = v; bidx = idx; }
    }

    for (int sel = 0; sel < TOPK; sel++) {
        // warp argmin over lane-cached segment minima
        float v = bv;
        int ix = bidx;
        #pragma unroll
        for (int off = 16; off; off >>= 1) {
            float vv = __shfl_xor_sync(0xffffffffu, v, off);
            int   ii = __shfl_xor_sync(0xffffffffu, ix, off);
            if (vv < v || (vv == v && ii < ix)) { v = vv; ix = ii; }
        }
        if (lane == 0) {
            g_eidx[(size_t)row * TOPK + sel] = ix;
            g_dn[(size_t)row * TOPK + sel] = v;
            if (writeIdx) outIdxF[(size_t)row * TOPK + sel] = (float)ix;
            D[ix] = INF;
        }
        __syncwarp();
        // rescan the winner's segment (owner lane = ix >> 6)
        int o = ix >> 6;
        int i2 = (o << 6) + 2 * lane;
        float2 pr = *(const float2*)&D[i2];
        float rv; int ridx;
        if (pr.x <= pr.y) { rv = pr.x; ridx = i2; }
        else { rv = pr.y; ridx = i2 + 1; }
        #pragma unroll
        for (int off = 16; off; off >>= 1) {
            float vv = __shfl_xor_sync(0xffffffffu, rv, off);
            int   ii = __shfl_xor_sync(0xffffffffu, ridx, off);
            if (vv < rv || (vv == rv && ii < ridx)) { rv = vv; ridx = ii; }
        }
        if (lane == o) { bv = rv; bidx = ridx; }
        __syncwarp();
    }
}

// ---------------- K4: mma.sync bf16-split GEMM + LN, 2 CTAs/SM (R9 proven version) ----------------
__global__ void __launch_bounds__(256, 2) gemm_mma_kernel(const float* __restrict__ gamma,
                                                          const float* __restrict__ beta,
                                                          float* __restrict__ out) {
    extern __shared__ char dyn[];
    __shared__ float sPos[128][16];
    __shared__ float sDist[128][25];
    __shared__ float sGam[128], sBet[128];
    __shared__ float sMu[128], sInv[128];

    char* Ah = dyn;                    // 128 x ASTRIDE bf16
    char* Al = dyn + ABYTES;
    char* Bh = dyn + 2 * ABYTES;       // 128(n) x ASTRIDE bf16
    char* Bl = dyn + 3 * ABYTES;
    float* E = (float*)dyn;            // epilogue reuse: 128 x ESTRIDE fp32

    int tile = blockIdx.x;
    int tid = threadIdx.x;
    int wid = tid >> 5, lane = tid & 31;
    int wm = wid >> 1, wn = wid & 1;

    // preamble
    if (tid < 128) {
        sGam[tid] = gamma[tid];
        sBet[tid] = beta[tid];
        int m = tid;
        int res = tile * 4 + (m >> 5);
        int e = m & 31;
        int bq = res >> 11;
        int i = res & (NRES - 1);
        int j = g_eidx[(size_t)res * TOPK + e];
        sDist[m][0] = g_dn[(size_t)res * TOPK + e];
        const float* AI = g_atoms + (size_t)res * 15;
        const float* AJ = g_atoms + (size_t)(bq * NRES + j) * 15;
        float ai[15], aj[15];
        #pragma unroll
        for (int t = 0; t < 15; t++) { ai[t] = AI[t]; aj[t] = AJ[t]; }
        #pragma unroll
        for (int p = 0; p < 24; p++) {
            int a3 = c_pa[p] * 3, b3 = c_pb[p] * 3;
            float dx = ai[a3 + 0] - aj[b3 + 0];
            float dy = ai[a3 + 1] - aj[b3 + 1];
            float dz = ai[a3 + 2] - aj[b3 + 2];
            sDist[m][1 + p] = sqrtf(dx * dx + dy * dy + dz * dz + 1e-6f);
        }
        float d = (float)(j - i);
        #pragma unroll
        for (int k = 0; k < 8; k++) {
            float s, c;
            sincosf(d * c_freq[k], &s, &c);
            sPos[m][k] = c;
            sPos[m][8 + k] = s;
        }
    }

    float acc[2][8][4];
    #pragma unroll
    for (int mi = 0; mi < 2; mi++)
        #pragma unroll
        for (int ni = 0; ni < 8; ni++)
            #pragma unroll
            for (int q = 0; q < 4; q++) acc[mi][ni][q] = 0.0f;

    for (int s = 0; s < NSTG; s++) {
        __syncthreads();   // prior compute done (and preamble on s=0)

        // ---- A fill: 128 rows x 64 cols of features, bf16 hi/lo ----
        for (int t = tid; t < 1024; t += 256) {
            int m = t >> 3;
            int g = t & 7;
            int k0 = s * 64 + g * 8;
            float v[8];
            if (k0 < 16) {
                #pragma unroll
                for (int q = 0; q < 8; q++) v[q] = sPos[m][k0 + q];
            } else if (k0 >= EIN) {
                #pragma unroll
                for (int q = 0; q < 8; q++) v[q] = 0.0f;
            } else {
                float Dv = (k0 < 32) ? sDist[m][0] : sDist[m][1 + ((k0 - 32) >> 4)];
                #pragma unroll
                for (int q = 0; q < 8; q++) {
                    int mth = (k0 + q) & 15;
                    float tt = (Dv - (2.0f + 1.3333333333f * (float)mth)) * 0.8f;
                    v[q] = __expf(-tt * tt);
                }
            }
            uint32_t hp[4], lp[4];
            #pragma unroll
            for (int q = 0; q < 4; q++) {
                float v0 = v[2 * q], v1 = v[2 * q + 1];
                __nv_bfloat16 h0 = __float2bfloat16(v0);
                __nv_bfloat16 h1 = __float2bfloat16(v1);
                __nv_bfloat162 h2; h2.x = h0; h2.y = h1;
                __nv_bfloat162 l2 = __floats2bfloat162_rn(v0 - __bfloat162float(h0),
                                                          v1 - __bfloat162float(h1));
                hp[q] = *(uint32_t*)&h2;
                lp[q] = *(uint32_t*)&l2;
            }
            *(uint4*)(Ah + m * 144 + g * 16) = make_uint4(hp[0], hp[1], hp[2], hp[3]);
            *(uint4*)(Al + m * 144 + g * 16) = make_uint4(lp[0], lp[1], lp[2], lp[3]);
        }
        // ---- B fill: copy stage image with stride padding ----
        {
            const uint32_t* srcH = (const uint32_t*)(g_Bhi + s * 8192);
            const uint32_t* srcL = (const uint32_t*)(g_Blo + s * 8192);
            for (int t = tid; t < 4096; t += 256) {
                int n = t >> 5, kp = t & 31;
                ((uint32_t*)Bh)[n * 36 + kp] = srcH[t];
                ((uint32_t*)Bl)[n * 36 + kp] = srcL[t];
            }
        }
        __syncthreads();

        // ---- compute: 4 k16-steps ----
        #pragma unroll
        for (int ks = 0; ks < 4; ks++) {
            uint32_t ahi[2][4], alo[2][4];
            #pragma unroll
            for (int mi = 0; mi < 2; mi++) {
                int rb = (wm * 32 + mi * 16 + (lane >> 2)) * 144 + ks * 32 + (lane & 3) * 4;
                ahi[mi][0] = *(const uint32_t*)(Ah + rb);
                ahi[mi][1] = *(const uint32_t*)(Ah + rb + 8 * 144);
                ahi[mi][2] = *(const uint32_t*)(Ah + rb + 16);
                ahi[mi][3] = *(const uint32_t*)(Ah + rb + 8 * 144 + 16);
                alo[mi][0] = *(const uint32_t*)(Al + rb);
                alo[mi][1] = *(const uint32_t*)(Al + rb + 8 * 144);
                alo[mi][2] = *(const uint32_t*)(Al + rb + 16);
                alo[mi][3] = *(const uint32_t*)(Al + rb + 8 * 144 + 16);
            }
            #pragma unroll
            for (int ni = 0; ni < 8; ni++) {
                int cb = (wn * 64 + ni * 8 + (lane >> 2)) * 144 + ks * 32 + (lane & 3) * 4;
                uint32_t bh0 = *(const uint32_t*)(Bh + cb);
                uint32_t bh1 = *(const uint32_t*)(Bh + cb + 16);
                uint32_t bl0 = *(const uint32_t*)(Bl + cb);
                uint32_t bl1 = *(const uint32_t*)(Bl + cb + 16);
                #pragma unroll
                for (int mi = 0; mi < 2; mi++) {
                    mma16816(acc[mi][ni], ahi[mi], bh0, bh1);
                    mma16816(acc[mi][ni], ahi[mi], bl0, bl1);
                    mma16816(acc[mi][ni], alo[mi], bh0, bh1);
                }
            }
        }
    }

    // ---- epilogue ----
    __syncthreads();
    #pragma unroll
    for (int mi = 0; mi < 2; mi++) {
        int r0 = wm * 32 + mi * 16 + (lane >> 2);
        #pragma unroll
        for (int ni = 0; ni < 8; ni++) {
            int c0 = wn * 64 + ni * 8 + (lane & 3) * 2;
            E[r0 * ESTRIDE + c0] = acc[mi][ni][0];
            E[r0 * ESTRIDE + c0 + 1] = acc[mi][ni][1];
            E[(r0 + 8) * ESTRIDE + c0] = acc[mi][ni][2];
            E[(r0 + 8) * ESTRIDE + c0 + 1] = acc[mi][ni][3];
        }
    }
    __syncthreads();

    if (tid < 128) {
        int r = tid;
        float sum = 0.0f, sq = 0.0f;
        #pragma unroll 16
        for (int c = 0; c < 128; c++) {
            float v = E[r * ESTRIDE + c];
            sum += v;
            sq += v * v;
        }
        float mu = sum * (1.0f / 128.0f);
        float var = sq * (1.0f / 128.0f) - mu * mu;
        sMu[r] = mu;
        sInv[r] = rsqrtf(fmaxf(var, 0.0f) + 1e-5f);
    }
    __syncthreads();

    for (int t = tid; t < 128 * 32; t += 256) {
        int m = t >> 5, q = t & 31;
        float mu = sMu[m], inv = sInv[m];
        float o0 = (E[m * ESTRIDE + q * 4 + 0] - mu) * inv * sGam[q * 4 + 0] + sBet[q * 4 + 0];
        float o1 = (E[m * ESTRIDE + q * 4 + 1] - mu) * inv * sGam[q * 4 + 1] + sBet[q * 4 + 1];
        float o2 = (E[m * ESTRIDE + q * 4 + 2] - mu) * inv * sGam[q * 4 + 2] + sBet[q * 4 + 2];
        float o3 = (E[m * ESTRIDE + q * 4 + 3] - mu) * inv * sGam[q * 4 + 3] + sBet[q * 4 + 3];
        float4 o = make_float4(o0, o1, o2, o3);
        *(float4*)(out + ((size_t)tile * 128 + m) * EFEAT + q * 4) = o;
    }
}

// ---------------- launch ----------------
extern "C" void kernel_launch(void* const* d_in, const int* in_sizes, int n_in,
                              void* d_out, int out_size) {
    const float* X = (const float*)d_in[0];
    const float* mask = (const float*)d_in[1];
    const float* W = (const float*)d_in[2];
    const float* gamma = (const float*)d_in[3];
    const float* beta = (const float*)d_in[4];
    float* out = (float*)d_out;

    const int E_ELEMS = NEDGE * EFEAT;
    int writeIdx = (out_size >= E_ELEMS + NEDGE) ? 1 : 0;
    float* outIdx = out + E_ELEMS;

    const int DYN = 4 * ABYTES;     // 73728
    const int TOPK_DYN = 98304;     // 12 * 2048 * 4
    cudaFuncSetAttribute(topk_kernel, cudaFuncAttributeMaxDynamicSharedMemorySize, TOPK_DYN);
    cudaFuncSetAttribute(gemm_mma_kernel, cudaFuncAttributeMaxDynamicSharedMemorySize, DYN);

    atoms_kernel<<<(NROWS + 255) / 256, 256>>>(X);
    prepw_kernel<<<(NSTG * 8192 + 255) / 256, 256>>>(W);
    topk_kernel<<<NROWS / 8, 256, TOPK_DYN>>>(mask, outIdx, writeIdx);
    gemm_mma_kernel<<<NEDGE / 128, 256, DYN>>>(gamma, beta, out);
}